// round 17
// baseline (speedup 1.0000x reference)
#include <cuda_runtime.h>
#include <cuda_fp16.h>
#include <cstdint>
#include <cstddef>

#define N_TOKENS   16384
#define IN_F       1024
#define OUT_F      1024
#define BH         32
#define BW         32
#define NB         256
#define N_RB       (OUT_F / BH)   // 32
#define N_TG       (N_TOKENS / 32) // 512 token groups
#define N_CB       (IN_F / 32)     // 32 col blocks
#define TOK_TILE   256
#define THREADS    256
#define SMAX       24             // W blocks per smem chunk (48KB of uint2 frags)
#define QX_BLOCKS  (N_TG * N_CB / 8)   // 2048 blocks of 8 warps for quantx

__device__ int g_cnt[N_RB];
__device__ int g_blk[N_RB][NB];
__device__ int g_col[N_RB][NB];
__device__ int g_rbmap[N_RB];
// W fragments: [b][s][nt][lane] = uint2{bm0, bm1} (fp16x2), 512KB
__device__ uint2 g_wq[NB * 2 * 4 * 32];
// x fragments, fragment-major: [unit = tg*32+cb][chunk = s*2+mt][lane] = uint4
__device__ uint4 g_xq[N_TG * N_CB * 4 * 32];   // 32 MB

// pack two floats -> fp16x2, LOWER-k element in LOW half.
__device__ __forceinline__ unsigned pack_f16(float hi, float lo) {
    unsigned d;
    asm("cvt.rn.f16x2.f32 %0, %1, %2;" : "=r"(d) : "f"(hi), "f"(lo));
    return d;
}

// ---- fused prepare: quantx (blocks 0..2047) + quantw (2048..2303) + prep (2304) ----
__global__ void spmm_prepare_kernel(const float* __restrict__ x,
                                    const float* __restrict__ w,
                                    const int* __restrict__ brow,
                                    const int* __restrict__ bcol) {
    const int bid = blockIdx.x;
    const int tid = threadIdx.x;

    if (bid < QX_BLOCKS) {
        // ---- quantx: one warp per (tg, cb) unit; write fragment-major fp16 ----
        const int wrp  = tid >> 5;
        const int lane = tid & 31;
        const int unit = bid * 8 + wrp;
        const int tg   = unit >> 5;
        const int cb   = unit & 31;
        const int g    = lane >> 2;
        const int c    = lane & 3;
        const float* xb = x + (size_t)(tg * 32) * IN_F + cb * 32;
#pragma unroll
        for (int s = 0; s < 2; ++s)
#pragma unroll
            for (int mt = 0; mt < 2; ++mt) {
                const float4 A0 = *(const float4*)(xb + (size_t)(mt * 16 + g)     * IN_F + 16 * s + 4 * c);
                const float4 A1 = *(const float4*)(xb + (size_t)(mt * 16 + 8 + g) * IN_F + 16 * s + 4 * c);
                g_xq[(unit * 4 + (s * 2 + mt)) * 32 + lane] =
                    make_uint4(pack_f16(A0.y, A0.x), pack_f16(A1.y, A1.x),
                               pack_f16(A0.w, A0.z), pack_f16(A1.w, A1.z));
            }
    } else if (bid < QX_BLOCKS + NB) {
        // ---- quantw: round + fragment-pack one W block ----
        const int b    = bid - QX_BLOCKS;
        const int s    = tid >> 7;
        const int nt   = (tid >> 5) & 3;
        const int lane = tid & 31;
        const int g    = lane >> 2;
        const int c    = lane & 3;
        const float4 f = *(const float4*)
            (w + (size_t)b * (BH * BW) + (nt * 8 + g) * BW + 16 * s + 4 * c);
        g_wq[((b * 2 + s) * 4 + nt) * 32 + lane] =
            make_uint2(pack_f16(f.y, f.x), pack_f16(f.w, f.z));
    } else {
        // ---- prep: ballot-based stable compaction + LPT sort (one block) ----
        __shared__ int whist[8][N_RB];
        __shared__ int scnt[N_RB];
        const int b    = tid;
        const int wrp  = b >> 5;
        const int lane = b & 31;
        for (int t = b; t < 8 * N_RB; t += THREADS) ((int*)whist)[t] = 0;
        __syncthreads();
        const int rb = brow[b];
        const unsigned mask = __match_any_sync(0xffffffffu, rb);
        const int lane_pos = __popc(mask & ((1u << lane) - 1u));
        if (lane_pos == 0) whist[wrp][rb] = __popc(mask);
        __syncthreads();
        int pos = lane_pos;
        for (int w2 = 0; w2 < wrp; ++w2) pos += whist[w2][rb];
        g_blk[rb][pos] = b;
        g_col[rb][pos] = bcol[b];
        if (b < N_RB) {
            int cc = 0;
#pragma unroll
            for (int w2 = 0; w2 < 8; ++w2) cc += whist[w2][b];
            g_cnt[b] = cc;
            scnt[b] = cc;
        }
        __syncthreads();
        if (b < N_RB) {
            int rank = 0;
            for (int j = 0; j < N_RB; ++j)
                rank += (scnt[j] > scnt[b]) || (scnt[j] == scnt[b] && j < b);
            g_rbmap[rank] = b;
        }
    }
}

__device__ __forceinline__ void mma_f16(float* d, const unsigned* a,
                                        unsigned b0, unsigned b1) {
    asm volatile(
        "mma.sync.aligned.m16n8k16.row.col.f32.f16.f16.f32 "
        "{%0,%1,%2,%3}, {%4,%5,%6,%7}, {%8,%9}, {%0,%1,%2,%3};"
        : "+f"(d[0]), "+f"(d[1]), "+f"(d[2]), "+f"(d[3])
        : "r"(a[0]), "r"(a[1]), "r"(a[2]), "r"(a[3]), "r"(b0), "r"(b1));
}

// ---- main: CTA = 256 tokens x one 32-wide row-block; 8 independent warps.
// Single-term fp16 (rel ~3e-4). A from fragment-major g_xq. 4 CTAs/SM
// (32 warps, 8/SMSP): per-s load/compute batches keep live regs <= 64.
__global__ __launch_bounds__(THREADS, 4)
void spmm_main_kernel(const float* __restrict__ bias,
                      float* __restrict__ out) {
    __shared__ alignas(16) uint2 smB[SMAX * 2 * 4 * 32];   // 48 KB

    const int rb   = g_rbmap[blockIdx.y];
    const int tok0 = blockIdx.x * TOK_TILE;
    const int tid  = threadIdx.x;
    const int wid  = tid >> 5;
    const int lane = tid & 31;
    const int g    = lane >> 2;   // 0..7
    const int c    = lane & 3;    // 0..3
    const int tgw  = blockIdx.x * 8 + wid;   // this warp's token group

    const int cnt = g_cnt[rb];

    float acc[2][4][4];
#pragma unroll
    for (int mt = 0; mt < 2; ++mt)
#pragma unroll
        for (int nt = 0; nt < 4; ++nt)
#pragma unroll
            for (int r = 0; r < 4; ++r) acc[mt][nt][r] = 0.0f;

    const uint4* xqw = &g_xq[(size_t)tgw * N_CB * 4 * 32 + lane];

    int done = 0;
    while (done < cnt) {
        const int n = (cnt - done < SMAX) ? (cnt - done) : SMAX;

        __syncthreads();   // previous chunk fully consumed
        for (int t = tid; t < n * 256; t += THREADS) {
            const int ii = t >> 8;
            const int r  = t & 255;
            smB[ii * 256 + r] = g_wq[g_blk[rb][done + ii] * 256 + r];
        }
        __syncthreads();

        int li = (wid + (int)blockIdx.x) % n;
        for (int step = 0; step < n; ++step) {
            const uint4* ap = xqw + (size_t)g_col[rb][done + li] * 128;

            // per-s batches: q (8 regs) + bv (8 regs), consumed immediately
#pragma unroll
            for (int s = 0; s < 2; ++s) {
                const uint4 q0 = ap[s * 64];        // (s, mt0)
                const uint4 q1 = ap[s * 64 + 32];   // (s, mt1)
                uint2 bv[4];
#pragma unroll
                for (int nt = 0; nt < 4; ++nt)
                    bv[nt] = smB[((li * 2 + s) * 4 + nt) * 32 + lane];
#pragma unroll
                for (int nt = 0; nt < 4; ++nt) {
                    mma_f16(acc[0][nt], (const unsigned*)&q0, bv[nt].x, bv[nt].y);
                    mma_f16(acc[1][nt], (const unsigned*)&q1, bv[nt].x, bv[nt].y);
                }
            }

            if (++li == n) li = 0;
        }
        done += n;
    }

    // ---- epilogue: add bias, store ----
    const float* bp = bias + rb * BH;
#pragma unroll
    for (int nt = 0; nt < 4; ++nt) {
        const float2 bv = *(const float2*)(bp + nt * 8 + 2 * c);
#pragma unroll
        for (int mt = 0; mt < 2; ++mt) {
            const int row0 = tok0 + wid * 32 + mt * 16 + g;
            float2 o0, o1;
            o0.x = acc[mt][nt][0] + bv.x;
            o0.y = acc[mt][nt][1] + bv.y;
            o1.x = acc[mt][nt][2] + bv.x;
            o1.y = acc[mt][nt][3] + bv.y;
            *(float2*)(out + (size_t)row0       * OUT_F + rb * BH + nt * 8 + 2 * c) = o0;
            *(float2*)(out + (size_t)(row0 + 8) * OUT_F + rb * BH + nt * 8 + 2 * c) = o1;
        }
    }
}

extern "C" void kernel_launch(void* const* d_in, const int* in_sizes, int n_in,
                              void* d_out, int out_size) {
    (void)in_sizes; (void)n_in; (void)out_size;
    const float* x    = (const float*)d_in[0];
    const float* w    = (const float*)d_in[1];
    const float* bias = (const float*)d_in[2];
    const int*   brow = (const int*)d_in[3];
    const int*   bcol = (const int*)d_in[4];
    float* out = (float*)d_out;

    spmm_prepare_kernel<<<QX_BLOCKS + NB + 1, THREADS>>>(x, w, brow, bcol);
    dim3 grid(N_TOKENS / TOK_TILE, N_RB);
    spmm_main_kernel<<<grid, THREADS>>>(bias, out);
}